// round 3
// baseline (speedup 1.0000x reference)
#include <cuda_runtime.h>
#include <cstdint>

// ============================================================================
// OneHotEncoding via uniform-grid nearest-neighbor search.
//
// Output layout (float32):
//   [0, 4L)            input_tensor: per point (x, y, z, one_hot)
//   [4L, 4L+3B)        closest_points [B,3]
//   [4L+3B, 4L+4B)     min_index as float [B]
//
// K1 count_kernel : histogram points into 32^3 cells + write pts part of out.
//                   Last-finishing block performs the exclusive scan, seeds
//                   the scatter cursors, re-zeros counts & the done counter
//                   (state self-resets => deterministic across graph replays).
// K2 scatter_kernel: reorder points into g_sorted[cell-major] (carries idx).
// K3 search_kernel : per-receiver expanding Chebyshev-ring search with exact
//                   lower bound; packed (d2bits<<32 | idx) u64 min gives
//                   argmin with first-index tie-break. Writes all tail outputs
//                   and scatters the one-hot 1.0s (+ reference's index-0 quirk).
// ============================================================================

#define GC        32                    // grid cells per dimension
#define CELLS     (GC * GC * GC)        // 32768
#define K1_GRID   152
#define K1_THREADS 512
#define CAP       1048576               // >= L (1e6)

__device__ unsigned int       g_cnt[CELLS];   // zero-init (.bss); self-resetting
__device__ unsigned int       g_cur[CELLS];   // scatter cursors -> inclusive ends
__device__ float4             g_sorted[CAP];  // (x, y, z, idx-as-bits)
__device__ unsigned int       g_done;         // zero-init; self-resetting

__device__ __forceinline__ int cell_of(float x) {
    int c = (int)(x * (float)GC);
    c = c < 0 ? 0 : c;
    return c > GC - 1 ? GC - 1 : c;
}

// ---------------------------------------------------------------------------
__global__ void __launch_bounds__(K1_THREADS)
count_kernel(const float* __restrict__ pts, float* __restrict__ out, int L)
{
    const int tid    = threadIdx.x;
    const int gid    = blockIdx.x * K1_THREADS + tid;
    const int stride = gridDim.x * K1_THREADS;

    for (int p = gid; p < L; p += stride) {
        float x = pts[3 * p + 0];
        float y = pts[3 * p + 1];
        float z = pts[3 * p + 2];
        // main output: (x, y, z, one_hot=0); K3 scatters the 1.0s later
        *reinterpret_cast<float4*>(out + 4 * (size_t)p) = make_float4(x, y, z, 0.0f);
        int c = (cell_of(z) * GC + cell_of(y)) * GC + cell_of(x);
        atomicAdd(&g_cnt[c], 1u);
    }

    // ---- last-block pattern: the final block to finish does the scan ----
    __threadfence();
    __syncthreads();
    __shared__ bool is_last;
    if (tid == 0) is_last = (atomicAdd(&g_done, 1u) == gridDim.x - 1);
    __syncthreads();
    if (!is_last) return;

    // exclusive scan of 32768 counts with 512 threads (64 cells each)
    __shared__ unsigned int ssum[K1_THREADS];
    const int PER  = CELLS / K1_THREADS;   // 64
    const int base = tid * PER;

    unsigned int acc = 0;
#pragma unroll 8
    for (int j = 0; j < PER; ++j) acc += g_cnt[base + j];
    ssum[tid] = acc;
    __syncthreads();

    // Hillis-Steele inclusive scan over 512 partials
    for (int off = 1; off < K1_THREADS; off <<= 1) {
        unsigned int v = (tid >= off) ? ssum[tid - off] : 0u;
        __syncthreads();
        ssum[tid] += v;
        __syncthreads();
    }

    unsigned int run = (tid > 0) ? ssum[tid - 1] : 0u;
#pragma unroll 8
    for (int j = 0; j < PER; ++j) {
        unsigned int c = g_cnt[base + j];
        g_cur[base + j] = run;       // exclusive start -> scatter cursor
        run += c;
        g_cnt[base + j] = 0u;        // reset for next graph replay
    }
    if (tid == 0) g_done = 0u;       // reset for next graph replay
}

// ---------------------------------------------------------------------------
__global__ void __launch_bounds__(K1_THREADS)
scatter_kernel(const float* __restrict__ pts, int L)
{
    const int gid    = blockIdx.x * K1_THREADS + threadIdx.x;
    const int stride = gridDim.x * K1_THREADS;

    for (int p = gid; p < L; p += stride) {
        float x = pts[3 * p + 0];
        float y = pts[3 * p + 1];
        float z = pts[3 * p + 2];
        int c = (cell_of(z) * GC + cell_of(y)) * GC + cell_of(x);
        unsigned int pos = atomicAdd(&g_cur[c], 1u);
        g_sorted[pos] = make_float4(x, y, z, __uint_as_float((unsigned int)p));
    }
    // post-condition: g_cur[c] == inclusive prefix end of cell c
}

// ---------------------------------------------------------------------------
// One block (128 threads = 4 warps) per receiver.
__global__ void __launch_bounds__(128)
search_kernel(const float* __restrict__ pts, const float* __restrict__ recv,
              float* __restrict__ out, int L, int B)
{
    const int b    = blockIdx.x;
    const int tid  = threadIdx.x;
    const int lane = tid & 31;
    const int wid  = tid >> 5;

    const float rx = recv[3 * b + 0];
    const float ry = recv[3 * b + 1];
    const float rz = recv[3 * b + 2];
    const int cx = cell_of(rx), cy = cell_of(ry), cz = cell_of(rz);

    const float H = 1.0f / (float)GC;

    unsigned long long best = ~0ull;            // (d2bits<<32 | idx); NaN d2
    unsigned long long blockbest = ~0ull;
    __shared__ unsigned long long s_best[4];

    for (int q = 0; q < GC; ++q) {
        if (q >= 1) {
            // exact bound: any ring-q cell is >= (q-1)*H away
            float bd = (float)(q - 1) * H;
            float bestd2 = __uint_as_float((unsigned int)(blockbest >> 32));
            if (bd * bd > bestd2) break;        // NaN-safe: false while no candidate
        }

        // enumerate surface cells of Chebyshev ring q, round-robin over warps
        int cno = 0;
        for (int dz = -q; dz <= q; ++dz) {
            int zz = cz + dz; if (zz < 0 || zz >= GC) continue;
            for (int dy = -q; dy <= q; ++dy) {
                int yy = cy + dy; if (yy < 0 || yy >= GC) continue;
                int m2 = max(abs(dz), abs(dy));
                for (int dx = -q; dx <= q; ++dx) {
                    if (max(m2, abs(dx)) != q) continue;     // surface only
                    int xx = cx + dx; if (xx < 0 || xx >= GC) continue;
                    if ((cno++ & 3) != wid) continue;        // my warp's cell?

                    int ci = (zz * GC + yy) * GC + xx;
                    unsigned int st = (ci > 0) ? g_cur[ci - 1] : 0u;
                    unsigned int en = g_cur[ci];
                    for (unsigned int i = st + lane; i < en; i += 32) {
                        float4 s = g_sorted[i];
                        float ddx = s.x - rx, ddy = s.y - ry, ddz = s.z - rz;
                        float d2  = ddx * ddx + ddy * ddy + ddz * ddz;
                        unsigned long long pk =
                            (((unsigned long long)__float_as_uint(d2)) << 32) |
                            (unsigned long long)__float_as_uint(s.w);
                        if (pk < best) best = pk;
                    }
                }
            }
        }

        // block-wide merge of this ring (warp shfl tree + smem)
        unsigned long long wb = best;
#pragma unroll
        for (int m = 16; m > 0; m >>= 1) {
            unsigned long long o = __shfl_xor_sync(0xffffffffu, wb, m);
            if (o < wb) wb = o;
        }
        if (lane == 0) s_best[wid] = wb;
        __syncthreads();
        unsigned long long bb = s_best[0];
#pragma unroll
        for (int w = 1; w < 4; ++w) if (s_best[w] < bb) bb = s_best[w];
        __syncthreads();                 // protect s_best reuse next ring
        best = bb;
        blockbest = bb;
    }

    if (tid == 0) {
        unsigned int idx = (unsigned int)(blockbest & 0xffffffffull);
        float* cp = out + 4 * (size_t)L;
        cp[3 * b + 0] = pts[3 * idx + 0];
        cp[3 * b + 1] = pts[3 * idx + 1];
        cp[3 * b + 2] = pts[3 * idx + 2];
        out[4 * (size_t)L + 3 * B + b] = (float)idx;   // min_index as float
        out[4 * (size_t)idx + 3] = 1.0f;               // one-hot scatter
        if (b == 0 && B > 1) out[3] = 1.0f;            // reference quirk
    }
}

// ---------------------------------------------------------------------------
extern "C" void kernel_launch(void* const* d_in, const int* in_sizes, int n_in,
                              void* d_out, int out_size)
{
    const float* pts  = (const float*)d_in[0];   // mesh_3D flattened [L,3]
    const float* recv = (const float*)d_in[1];   // receiver_pos [B,3]
    float* out = (float*)d_out;

    int L = in_sizes[0] / 3;   // 1,000,000
    int B = in_sizes[1] / 3;   // 128

    count_kernel  <<<K1_GRID, K1_THREADS>>>(pts, out, L);
    scatter_kernel<<<K1_GRID, K1_THREADS>>>(pts, L);
    search_kernel <<<B, 128>>>(pts, recv, out, L, B);
}

// round 4
// speedup vs baseline: 3.3832x; 3.3832x over previous
#include <cuda_runtime.h>
#include <cstdint>

// ============================================================================
// OneHotEncoding via receiver-box candidate filtering (no index build).
//
// Output layout (float32):
//   [0, 4L)            input_tensor: per point (x, y, z, one_hot)
//   [4L, 4L+3B)        closest_points [B,3]
//   [4L+3B, 4L+4B)     min_index as float [B]
//
// K1 ub_kernel    : per receiver, exact min over first SAMPLES points; seeds
//                   g_best[r] with a VALID packed (d2<<32|idx) upper bound.
// K2 lists_kernel : 16^3 cell -> list of receivers whose [r-UB, r+UB]^3 box
//                   intersects the cell. Thread-per-cell, no atomics.
//                   Unconditionally correct: true NN is within UB of r.
// K3 main_kernel  : stream pts once; write out[L,4]; for receivers listed in
//                   the point's cell, eval d2 and atomicMin packed u64 (rare).
// K4 fin_kernel   : closest_points, min_index, one-hot scatter + index-0 quirk.
//
// No global-atomic hot spots (R3 lesson: small shared atomic tables serialize
// in the LTS at ~32cyc/op/line). All device state fully rewritten per replay.
// ============================================================================

#define GC       16
#define CELLS    (GC * GC * GC)        // 4096
#define MAXB     128
#define SAMPLES  16384

__device__ unsigned long long g_best[MAXB];          // packed (d2bits<<32 | idx)
__device__ unsigned int       g_lcnt[CELLS];         // receivers per cell
__device__ unsigned char      g_list[CELLS * MAXB];  // receiver ids per cell

__device__ __forceinline__ int cell_clamp(int c) {
    c = c < 0 ? 0 : c;
    return c > GC - 1 ? GC - 1 : c;
}
__device__ __forceinline__ int cell_of(float x) {
    return cell_clamp((int)floorf(x * (float)GC));
}

// ---------------------------------------------------------------------------
// K1: one block per receiver; exact brute-force min over first n sample points.
__global__ void __launch_bounds__(256)
ub_kernel(const float* __restrict__ pts, const float* __restrict__ recv, int L)
{
    const int b   = blockIdx.x;
    const int tid = threadIdx.x;
    const float rx = recv[3 * b + 0];
    const float ry = recv[3 * b + 1];
    const float rz = recv[3 * b + 2];

    const int n = (L < SAMPLES) ? L : SAMPLES;
    unsigned long long best = ~0ull;
    for (int p = tid; p < n; p += 256) {
        float dx = pts[3 * p + 0] - rx;
        float dy = pts[3 * p + 1] - ry;
        float dz = pts[3 * p + 2] - rz;
        float d2 = dx * dx + dy * dy + dz * dz;
        unsigned long long pk =
            (((unsigned long long)__float_as_uint(d2)) << 32) |
            (unsigned long long)(unsigned int)p;
        if (pk < best) best = pk;
    }
#pragma unroll
    for (int m = 16; m > 0; m >>= 1) {
        unsigned long long o = __shfl_xor_sync(0xffffffffu, best, m);
        if (o < best) best = o;
    }
    __shared__ unsigned long long s_b[8];
    if ((tid & 31) == 0) s_b[tid >> 5] = best;
    __syncthreads();
    if (tid == 0) {
        unsigned long long bb = s_b[0];
#pragma unroll
        for (int w = 1; w < 8; ++w) if (s_b[w] < bb) bb = s_b[w];
        g_best[b] = bb;                 // valid upper bound (actual point)
    }
}

// ---------------------------------------------------------------------------
// K2: thread-per-cell; build cell -> receiver candidate lists. No atomics.
__global__ void __launch_bounds__(512)
lists_kernel(const float* __restrict__ recv, int B)
{
    __shared__ int s_lx[MAXB], s_hx[MAXB], s_ly[MAXB], s_hy[MAXB],
                   s_lz[MAXB], s_hz[MAXB];
    const int tid = threadIdx.x;

    if (tid < B) {
        float ub2 = __uint_as_float((unsigned int)(g_best[tid] >> 32));
        float ub  = sqrtf(ub2) * 1.0001f + 1e-7f;   // ulp guard
        float rx = recv[3 * tid + 0];
        float ry = recv[3 * tid + 1];
        float rz = recv[3 * tid + 2];
        s_lx[tid] = cell_of(rx - ub);  s_hx[tid] = cell_of(rx + ub);
        s_ly[tid] = cell_of(ry - ub);  s_hy[tid] = cell_of(ry + ub);
        s_lz[tid] = cell_of(rz - ub);  s_hz[tid] = cell_of(rz + ub);
    }
    __syncthreads();

    const int cell = blockIdx.x * 512 + tid;        // 8 blocks x 512 = 4096
    if (cell >= CELLS) return;
    const int cx = cell & (GC - 1);
    const int cy = (cell >> 4) & (GC - 1);
    const int cz = cell >> 8;

    unsigned int n = 0;
    for (int r = 0; r < B; ++r) {
        bool hit = (cx >= s_lx[r]) & (cx <= s_hx[r]) &
                   (cy >= s_ly[r]) & (cy <= s_hy[r]) &
                   (cz >= s_lz[r]) & (cz <= s_hz[r]);
        if (hit) g_list[cell * MAXB + n++] = (unsigned char)r;
    }
    g_lcnt[cell] = n;
}

// ---------------------------------------------------------------------------
// K3: stream all points once; write out[L,4]; rare candidate evals + atomics.
__global__ void __launch_bounds__(512)
main_kernel(const float* __restrict__ pts, const float* __restrict__ recv,
            float* __restrict__ out, int L, int B)
{
    __shared__ float srx[MAXB], sry[MAXB], srz[MAXB];
    const int tid = threadIdx.x;
    if (tid < B) {
        srx[tid] = recv[3 * tid + 0];
        sry[tid] = recv[3 * tid + 1];
        srz[tid] = recv[3 * tid + 2];
    }
    __syncthreads();

    const int nGrp   = (L + 3) >> 2;                 // groups of 4 points
    const int gid    = blockIdx.x * 512 + tid;
    const int stride = gridDim.x * 512;

    for (int g = gid; g < nGrp; g += stride) {
        const int p0 = 4 * g;
        float x[4], y[4], z[4];
        if (p0 + 3 < L) {                            // fast path: 3x float4
            const float4* src = reinterpret_cast<const float4*>(pts + 3 * p0);
            float4 a = src[0], bq = src[1], c = src[2];
            x[0]=a.x;  y[0]=a.y;  z[0]=a.z;
            x[1]=a.w;  y[1]=bq.x; z[1]=bq.y;
            x[2]=bq.z; y[2]=bq.w; z[2]=c.x;
            x[3]=c.y;  y[3]=c.z;  z[3]=c.w;
        } else {
#pragma unroll
            for (int j = 0; j < 4; ++j) {
                int p = p0 + j;
                x[j] = (p < L) ? pts[3 * p + 0] : 2.0f;   // 2.0 -> never listed
                y[j] = (p < L) ? pts[3 * p + 1] : 2.0f;
                z[j] = (p < L) ? pts[3 * p + 2] : 2.0f;
            }
        }

#pragma unroll
        for (int j = 0; j < 4; ++j) {
            const int p = p0 + j;
            if (p >= L) break;
            *reinterpret_cast<float4*>(out + 4 * (size_t)p) =
                make_float4(x[j], y[j], z[j], 0.0f);

            int c = (cell_of(z[j]) * GC + cell_of(y[j])) * GC + cell_of(x[j]);
            unsigned int n = g_lcnt[c];
            for (unsigned int k = 0; k < n; ++k) {
                int r = g_list[c * MAXB + k];
                float dx = x[j] - srx[r];
                float dy = y[j] - sry[r];
                float dz = z[j] - srz[r];
                float d2 = dx * dx + dy * dy + dz * dz;
                unsigned long long pk =
                    (((unsigned long long)__float_as_uint(d2)) << 32) |
                    (unsigned long long)(unsigned int)p;
                // stale-high read is safe: atomicMin is authoritative
                if (pk < g_best[r]) atomicMin(&g_best[r], pk);
            }
        }
    }
}

// ---------------------------------------------------------------------------
__global__ void fin_kernel(const float* __restrict__ pts,
                           float* __restrict__ out, int L, int B)
{
    int t = threadIdx.x;
    if (t < B) {
        unsigned int idx = (unsigned int)(g_best[t] & 0xffffffffull);
        float* cp = out + 4 * (size_t)L;
        cp[3 * t + 0] = pts[3 * idx + 0];
        cp[3 * t + 1] = pts[3 * idx + 1];
        cp[3 * t + 2] = pts[3 * idx + 2];
        out[4 * (size_t)L + 3 * B + t] = (float)idx;   // min_index as float
        out[4 * (size_t)idx + 3] = 1.0f;               // one-hot scatter
    }
    if (t == 0 && B > 1) out[3] = 1.0f;                // reference quirk
}

// ---------------------------------------------------------------------------
extern "C" void kernel_launch(void* const* d_in, const int* in_sizes, int n_in,
                              void* d_out, int out_size)
{
    const float* pts  = (const float*)d_in[0];   // mesh_3D flattened [L,3]
    const float* recv = (const float*)d_in[1];   // receiver_pos [B,3]
    float* out = (float*)d_out;

    int L = in_sizes[0] / 3;   // 1,000,000
    int B = in_sizes[1] / 3;   // 128

    ub_kernel   <<<B, 256>>>(pts, recv, L);
    lists_kernel<<<(CELLS + 511) / 512, 512>>>(recv, B);
    main_kernel <<<152, 512>>>(pts, recv, out, L, B);
    fin_kernel  <<<1, 128>>>(pts, out, L, B);
}